// round 14
// baseline (speedup 1.0000x reference)
#include <cuda_runtime.h>
#include <cuda_bf16.h>
#include <cstdint>

// out[b,p,h] = sum_{i,j} premise[b,p,i] * kernel[p,h,i,j] * hypothesis[b,h,j]
// B=8, P=96, H=96, D1=D2=128
//
// HBM-bound (604 MB K streamed once). R13 proven core: 4-stage x 8 KB
// cp.async.bulk rolling ring in smem (40 KB/CTA -> 5 CTAs/SM, 160 KB/SM in
// flight off the register file), zero-pack f32x2 mainloop.
//
// R14 change: each CTA processes FOUR consecutive h tiles (kernel[p,h0..h0+3]
// is one contiguous 256 KB block) as ONE continuous 32-chunk stream through
// the same ring. Chunk gc+4 is issued before tile gc/8's epilogue runs, so
// per-tile prologue DRAM latency is hidden behind the previous tile's
// epilogue; only one cold start + one drain per 256 KB remain.

#define NB 8
#define NP 96
#define NH 96
#define ND 128

#define TILES_PC   4             // h tiles per CTA
#define STAGES     4
#define CHUNK_B    8192          // 16 rows * 512 B
#define CHUNK_ROWS 16
#define NCHUNKS_T  8             // chunks per tile
#define NCHUNKS_ALL (TILES_PC * NCHUNKS_T)   // 32

#define BAR_OFF 0                // 4 mbarriers * 8 B
#define PRE_OFF 128              // 8 KB dup premise
#define K_OFF   (PRE_OFF + 8192) // 32 KB ring
#define SMEM_TOTAL (K_OFF + STAGES * CHUNK_B)   // 41088 B

using u64 = unsigned long long;

__device__ __forceinline__ u64 fma2(u64 a, u64 b, u64 c) {
    u64 d;
    asm("fma.rn.f32x2 %0, %1, %2, %3;" : "=l"(d) : "l"(a), "l"(b), "l"(c));
    return d;
}
__device__ __forceinline__ u64 dup2(float v) {
    u64 r;
    asm("mov.b64 %0, {%1, %1};" : "=l"(r) : "f"(v));
    return r;
}
__device__ __forceinline__ void unpack2(u64 v, float& lo, float& hi) {
    asm("mov.b64 {%0, %1}, %2;" : "=f"(lo), "=f"(hi) : "l"(v));
}
__device__ __forceinline__ uint32_t smem_u32(const void* p) {
    uint32_t a;
    asm("{ .reg .u64 t; cvta.to.shared.u64 t, %1; cvt.u32.u64 %0, t; }"
        : "=r"(a) : "l"(p));
    return a;
}
__device__ __forceinline__ void mbar_wait(uint32_t mbar, uint32_t parity) {
    asm volatile(
        "{\n\t"
        ".reg .pred P1;\n\t"
        "WL_%=:\n\t"
        "mbarrier.try_wait.parity.acquire.cta.shared::cta.b64 P1, [%0], %1, 0x989680;\n\t"
        "@P1 bra.uni WD_%=;\n\t"
        "bra.uni WL_%=;\n\t"
        "WD_%=:\n\t"
        "}"
        :: "r"(mbar), "r"(parity) : "memory");
}
__device__ __forceinline__ void issue_chunk(uint32_t bar, uint32_t dst,
                                            const unsigned char* src) {
    asm volatile("mbarrier.arrive.expect_tx.shared.b64 _, [%0], %1;"
                 :: "r"(bar), "r"(CHUNK_B) : "memory");
    asm volatile(
        "cp.async.bulk.shared::cluster.global.mbarrier::complete_tx::bytes "
        "[%0], [%1], %2, [%3];"
        :: "r"(dst), "l"(src), "r"(CHUNK_B), "r"(bar) : "memory");
}

__global__ void __launch_bounds__(128)
interaction_kernel(const float* __restrict__ premise,
                   const float* __restrict__ hyp,
                   const float* __restrict__ kern,
                   float* __restrict__ out)
{
    extern __shared__ __align__(128) unsigned char smem_raw[];

    const int h0  = blockIdx.x * TILES_PC;   // 0,4,..,92
    const int p   = blockIdx.y;              // 0..95
    const int tid = threadIdx.x;             // 0..127
    const int w   = tid >> 5;                // warp: rows ir ≡ w (mod 4)
    const int l   = tid & 31;                // lane: columns 4l..4l+3

    const uint32_t sbase = smem_u32(smem_raw);
    u64* pre_d = reinterpret_cast<u64*>(smem_raw + PRE_OFF);
    __shared__ float red[4][NB];

    // 256 KB contiguous K block for tiles h0..h0+3
    const unsigned char* ksrc = reinterpret_cast<const unsigned char*>(
        kern + (((size_t)(p * NH + h0)) << 14));

    if (tid == 0) {
#pragma unroll
        for (int s = 0; s < STAGES; s++)
            asm volatile("mbarrier.init.shared.b64 [%0], %1;"
                         :: "r"(sbase + BAR_OFF + 8 * s), "r"(1) : "memory");
    }
    __syncthreads();

    // Prologue: fill the ring (chunks 0..3).
    if (tid == 0) {
#pragma unroll
        for (int s = 0; s < STAGES; s++)
            issue_chunk(sbase + BAR_OFF + 8 * s,
                        sbase + K_OFF + s * CHUNK_B,
                        ksrc + (size_t)s * CHUNK_B);
    }

    // Stage premise[:, p, :] duplicated (p fixed for all 4 tiles).
#pragma unroll
    for (int r = 0; r < 8; r++) {
        int idx = tid + r * 128;
        int i = idx >> 3;
        int b = idx & 7;
        pre_d[idx] = dup2(premise[((size_t)b * NP + p) * ND + i]);
    }
    __syncthreads();

    const ulonglong2* pre2 = reinterpret_cast<const ulonglong2*>(pre_d);
    const ulonglong2* kbuf = reinterpret_cast<const ulonglong2*>(smem_raw + K_OFF);

    for (int tt = 0; tt < TILES_PC; tt++) {
        const int h = h0 + tt;

        u64 acc[NB][2];
#pragma unroll
        for (int b = 0; b < NB; b++) { acc[b][0] = 0ull; acc[b][1] = 0ull; }

#pragma unroll
        for (int c = 0; c < NCHUNKS_T; c++) {
            const int gc    = tt * NCHUNKS_T + c;     // global chunk 0..31
            const int stage = gc & (STAGES - 1);
            mbar_wait(sbase + BAR_OFF + 8 * stage, (gc >> 2) & 1);

#pragma unroll
            for (int r = 0; r < CHUNK_ROWS / 4; r++) {
                const int ir = w + 4 * r;             // row within chunk
                const int i  = c * CHUNK_ROWS + ir;   // row within tile
                ulonglong2 kv = kbuf[stage * 512 + ir * 32 + l];  // LDS.128
                ulonglong2 pr01 = pre2[i * 4 + 0];    // broadcast LDS.128
                ulonglong2 pr23 = pre2[i * 4 + 1];
                ulonglong2 pr45 = pre2[i * 4 + 2];
                ulonglong2 pr67 = pre2[i * 4 + 3];
                u64 pr[NB] = { pr01.x, pr01.y, pr23.x, pr23.y,
                               pr45.x, pr45.y, pr67.x, pr67.y };
#pragma unroll
                for (int b = 0; b < NB; b++) {
                    acc[b][0] = fma2(kv.x, pr[b], acc[b][0]);
                    acc[b][1] = fma2(kv.y, pr[b], acc[b][1]);
                }
            }

            // Recycle this stage for chunk gc+4 (safe after full-CTA sync).
            if (gc < NCHUNKS_ALL - STAGES) {
                __syncthreads();
                if (tid == 0)
                    issue_chunk(sbase + BAR_OFF + 8 * stage,
                                sbase + K_OFF + stage * CHUNK_B,
                                ksrc + (size_t)(gc + STAGES) * CHUNK_B);
            }
        }

        // Epilogue for tile h — overlaps with in-flight TMA of next tile.
        float s[NB];
#pragma unroll
        for (int b = 0; b < NB; b++) {
            ulonglong2 hv = *reinterpret_cast<const ulonglong2*>(
                &hyp[((size_t)b * NH + h) * ND + 4 * l]);
            u64 t = fma2(acc[b][0], hv.x, 0ull);
            t = fma2(acc[b][1], hv.y, t);
            float lo, hi;
            unpack2(t, lo, hi);
            s[b] = lo + hi;
        }

#pragma unroll
        for (int off = 16; off; off >>= 1) {
#pragma unroll
            for (int b = 0; b < NB; b++)
                s[b] += __shfl_down_sync(0xffffffffu, s[b], off);
        }

        if (l == 0) {
#pragma unroll
            for (int b = 0; b < NB; b++) red[w][b] = s[b];
        }
        __syncthreads();

        if (tid < NB) {
            float v = red[0][tid] + red[1][tid] + red[2][tid] + red[3][tid];
            out[((size_t)tid * NP + p) * NH + h] = v;
        }
        __syncthreads();   // red[] safe for next tile
    }
}

extern "C" void kernel_launch(void* const* d_in, const int* in_sizes, int n_in,
                              void* d_out, int out_size) {
    const float* premise = (const float*)d_in[0];  // (8, 96, 128)
    const float* hyp     = (const float*)d_in[1];  // (8, 96, 128)
    const float* kern    = (const float*)d_in[2];  // (96, 96, 128, 128)
    float* out = (float*)d_out;                    // (8, 96, 96)

    cudaFuncSetAttribute(interaction_kernel,
                         cudaFuncAttributeMaxDynamicSharedMemorySize, SMEM_TOTAL);
    dim3 grid(NH / TILES_PC, NP);
    interaction_kernel<<<grid, 128, SMEM_TOTAL>>>(premise, hyp, kern, out);
}

// round 15
// speedup vs baseline: 1.0671x; 1.0671x over previous
#include <cuda_runtime.h>
#include <cuda_bf16.h>
#include <cstdint>

// out[b,p,h] = sum_{i,j} premise[b,p,i] * kernel[p,h,i,j] * hypothesis[b,h,j]
// B=8, P=96, H=96, D1=D2=128
//
// HBM-bound (604 MB K streamed once). R13 proven core: one CTA per (p,h)
// (9216 CTAs — CTA churn hides tile boundaries; R14 multi-tile regressed),
// 4-stage x 8 KB cp.async.bulk ring (40 KB smem -> 5 CTAs/SM, 160 KB/SM in
// flight off the register file), zero-pack f32x2 mainloop.
//
// R15 change: per-chunk __syncthreads replaced by a producer/consumer
// empty-mbarrier (arrive count 4, one arrive per warp). Consumers never
// converge — a warp arrives and immediately waits on the NEXT chunk's full
// barrier; only warp 0 waits for empty[stage] before lane 0 re-issues
// chunk c+4. Warp skew no longer gates consumption or TMA issue.

#define NB 8
#define NP 96
#define NH 96
#define ND 128

#define STAGES     4
#define NCHUNKS    8
#define CHUNK_B    8192          // 16 rows * 512 B
#define CHUNK_ROWS 16

#define FULL_OFF  0              // 4 full mbarriers * 8 B
#define EMPTY_OFF 32             // 4 empty mbarriers * 8 B
#define PRE_OFF   128            // 8 KB dup premise
#define K_OFF     (PRE_OFF + 8192)  // 32 KB ring
#define SMEM_TOTAL (K_OFF + STAGES * CHUNK_B)   // 41088 B

using u64 = unsigned long long;

__device__ __forceinline__ u64 fma2(u64 a, u64 b, u64 c) {
    u64 d;
    asm("fma.rn.f32x2 %0, %1, %2, %3;" : "=l"(d) : "l"(a), "l"(b), "l"(c));
    return d;
}
__device__ __forceinline__ u64 dup2(float v) {
    u64 r;
    asm("mov.b64 %0, {%1, %1};" : "=l"(r) : "f"(v));
    return r;
}
__device__ __forceinline__ void unpack2(u64 v, float& lo, float& hi) {
    asm("mov.b64 {%0, %1}, %2;" : "=f"(lo), "=f"(hi) : "l"(v));
}
__device__ __forceinline__ uint32_t smem_u32(const void* p) {
    uint32_t a;
    asm("{ .reg .u64 t; cvta.to.shared.u64 t, %1; cvt.u32.u64 %0, t; }"
        : "=r"(a) : "l"(p));
    return a;
}
__device__ __forceinline__ void mbar_wait(uint32_t mbar, uint32_t parity) {
    asm volatile(
        "{\n\t"
        ".reg .pred P1;\n\t"
        "WL_%=:\n\t"
        "mbarrier.try_wait.parity.acquire.cta.shared::cta.b64 P1, [%0], %1, 0x989680;\n\t"
        "@P1 bra.uni WD_%=;\n\t"
        "bra.uni WL_%=;\n\t"
        "WD_%=:\n\t"
        "}"
        :: "r"(mbar), "r"(parity) : "memory");
}
__device__ __forceinline__ void mbar_arrive(uint32_t mbar) {
    asm volatile("mbarrier.arrive.release.cta.shared::cta.b64 _, [%0];"
                 :: "r"(mbar) : "memory");
}
__device__ __forceinline__ void issue_chunk(uint32_t bar, uint32_t dst,
                                            const unsigned char* src) {
    asm volatile("mbarrier.arrive.expect_tx.shared.b64 _, [%0], %1;"
                 :: "r"(bar), "r"(CHUNK_B) : "memory");
    asm volatile(
        "cp.async.bulk.shared::cluster.global.mbarrier::complete_tx::bytes "
        "[%0], [%1], %2, [%3];"
        :: "r"(dst), "l"(src), "r"(CHUNK_B), "r"(bar) : "memory");
}

__global__ void __launch_bounds__(128)
interaction_kernel(const float* __restrict__ premise,
                   const float* __restrict__ hyp,
                   const float* __restrict__ kern,
                   float* __restrict__ out)
{
    extern __shared__ __align__(128) unsigned char smem_raw[];

    const int h   = blockIdx.x;      // 0..95
    const int p   = blockIdx.y;      // 0..95
    const int tid = threadIdx.x;     // 0..127
    const int w   = tid >> 5;        // warp: rows ir ≡ w (mod 4) within chunk
    const int l   = tid & 31;        // lane: columns 4l..4l+3

    const uint32_t sbase = smem_u32(smem_raw);
    u64* pre_d = reinterpret_cast<u64*>(smem_raw + PRE_OFF);
    __shared__ float red[4][NB];

    const unsigned char* ksrc = reinterpret_cast<const unsigned char*>(
        kern + (((size_t)(p * NH + h)) << 14));

    // full[s]: TMA completion (arrive count 1 = expect_tx arrival).
    // empty[s]: stage drained (arrive count 4 = one per warp).
    if (tid == 0) {
#pragma unroll
        for (int s = 0; s < STAGES; s++) {
            asm volatile("mbarrier.init.shared.b64 [%0], %1;"
                         :: "r"(sbase + FULL_OFF + 8 * s), "r"(1) : "memory");
            asm volatile("mbarrier.init.shared.b64 [%0], %1;"
                         :: "r"(sbase + EMPTY_OFF + 8 * s), "r"(4) : "memory");
        }
    }
    __syncthreads();

    // Prologue: fill the ring (chunks 0..3 -> stages 0..3, fresh stages).
    if (tid == 0) {
#pragma unroll
        for (int s = 0; s < STAGES; s++)
            issue_chunk(sbase + FULL_OFF + 8 * s,
                        sbase + K_OFF + s * CHUNK_B,
                        ksrc + (size_t)s * CHUNK_B);
    }

    // Stage premise[:, p, :] duplicated: pre_d[i*8+b] = (v, v)
#pragma unroll
    for (int r = 0; r < 8; r++) {
        int idx = tid + r * 128;
        int i = idx >> 3;
        int b = idx & 7;
        pre_d[idx] = dup2(premise[((size_t)b * NP + p) * ND + i]);
    }
    __syncthreads();

    const ulonglong2* pre2 = reinterpret_cast<const ulonglong2*>(pre_d);
    const ulonglong2* kbuf = reinterpret_cast<const ulonglong2*>(smem_raw + K_OFF);

    // acc[b][jp]: f32x2 accumulator for columns (4l+2jp, 4l+2jp+1), batch b
    u64 acc[NB][2];
#pragma unroll
    for (int b = 0; b < NB; b++) { acc[b][0] = 0ull; acc[b][1] = 0ull; }

#pragma unroll
    for (int c = 0; c < NCHUNKS; c++) {
        const int stage = c & (STAGES - 1);
        mbar_wait(sbase + FULL_OFF + 8 * stage, (c >= STAGES) ? 1u : 0u);

#pragma unroll
        for (int r = 0; r < CHUNK_ROWS / 4; r++) {
            const int ir = w + 4 * r;                 // row within chunk
            const int i  = c * CHUNK_ROWS + ir;       // row within tile
            ulonglong2 kv = kbuf[stage * 512 + ir * 32 + l];  // LDS.128
            ulonglong2 pr01 = pre2[i * 4 + 0];        // broadcast LDS.128
            ulonglong2 pr23 = pre2[i * 4 + 1];
            ulonglong2 pr45 = pre2[i * 4 + 2];
            ulonglong2 pr67 = pre2[i * 4 + 3];
            u64 pr[NB] = { pr01.x, pr01.y, pr23.x, pr23.y,
                           pr45.x, pr45.y, pr67.x, pr67.y };
#pragma unroll
            for (int b = 0; b < NB; b++) {
                acc[b][0] = fma2(kv.x, pr[b], acc[b][0]);
                acc[b][1] = fma2(kv.y, pr[b], acc[b][1]);
            }
        }

        if (c < NCHUNKS - STAGES) {
            // Each warp signals this stage drained; no CTA-wide convergence.
            if (l == 0) mbar_arrive(sbase + EMPTY_OFF + 8 * stage);
            // Warp 0 alone waits for all 4 drains, then lane 0 re-issues.
            if (w == 0) {
                mbar_wait(sbase + EMPTY_OFF + 8 * stage, 0);
                if (l == 0)
                    issue_chunk(sbase + FULL_OFF + 8 * stage,
                                sbase + K_OFF + stage * CHUNK_B,
                                ksrc + (size_t)(c + STAGES) * CHUNK_B);
            }
        }
    }

    // Epilogue: fold hypothesis[b, h, 4l..4l+3] (float4 = two f32x2 pairs)
    float s[NB];
#pragma unroll
    for (int b = 0; b < NB; b++) {
        ulonglong2 hv = *reinterpret_cast<const ulonglong2*>(
            &hyp[((size_t)b * NH + h) * ND + 4 * l]);
        u64 t = fma2(acc[b][0], hv.x, 0ull);
        t = fma2(acc[b][1], hv.y, t);
        float lo, hi;
        unpack2(t, lo, hi);
        s[b] = lo + hi;
    }

    // Reduce over 32 lanes (j dimension)
#pragma unroll
    for (int off = 16; off; off >>= 1) {
#pragma unroll
        for (int b = 0; b < NB; b++)
            s[b] += __shfl_down_sync(0xffffffffu, s[b], off);
    }

    if (l == 0) {
#pragma unroll
        for (int b = 0; b < NB; b++) red[w][b] = s[b];
    }
    __syncthreads();

    if (tid < NB) {
        float v = red[0][tid] + red[1][tid] + red[2][tid] + red[3][tid];
        out[((size_t)tid * NP + p) * NH + h] = v;
    }
}

extern "C" void kernel_launch(void* const* d_in, const int* in_sizes, int n_in,
                              void* d_out, int out_size) {
    const float* premise = (const float*)d_in[0];  // (8, 96, 128)
    const float* hyp     = (const float*)d_in[1];  // (8, 96, 128)
    const float* kern    = (const float*)d_in[2];  // (96, 96, 128, 128)
    float* out = (float*)d_out;                    // (8, 96, 96)

    cudaFuncSetAttribute(interaction_kernel,
                         cudaFuncAttributeMaxDynamicSharedMemorySize, SMEM_TOTAL);
    dim3 grid(NH, NP);
    interaction_kernel<<<grid, 128, SMEM_TOTAL>>>(premise, hyp, kern, out);
}

// round 16
// speedup vs baseline: 1.0900x; 1.0215x over previous
#include <cuda_runtime.h>
#include <cuda_bf16.h>
#include <cstdint>

// out[b,p,h] = sum_{i,j} premise[b,p,i] * kernel[p,h,i,j] * hypothesis[b,h,j]
// B=8, P=96, H=96, D1=D2=128
//
// HBM-bound (604 MB K streamed once). Proven R13 core: one CTA per (p,h)
// (9216 CTAs — churn hides tile boundaries), cp.async.bulk rolling ring with
// per-chunk __syncthreads recycle (beat the mbarrier empty-barrier protocol
// in R15), zero-pack f32x2 mainloop.
//
// R16 change: ring 4 -> 3 stages (24 KB). smem 41 KB -> 32.9 KB per CTA
// => 6 CTAs/SM (was 5): 24 consumer warps and 6 staggered chunk streams,
// in-flight bytes still 6 x 24 KB = 144 KB/SM >> bandwidth-delay product.
// Stage index (c % 3) and parity ((c/3) & 1) are compile-time constants
// under the fully unrolled 8-chunk loop.

#define NB 8
#define NP 96
#define NH 96
#define ND 128

#define STAGES     3
#define NCHUNKS    8
#define CHUNK_B    8192          // 16 rows * 512 B
#define CHUNK_ROWS 16

#define BAR_OFF 0                // 3 mbarriers * 8 B
#define PRE_OFF 128              // 8 KB dup premise
#define K_OFF   (PRE_OFF + 8192) // 24 KB ring
#define SMEM_TOTAL (K_OFF + STAGES * CHUNK_B)   // 32896 B

using u64 = unsigned long long;

__device__ __forceinline__ u64 fma2(u64 a, u64 b, u64 c) {
    u64 d;
    asm("fma.rn.f32x2 %0, %1, %2, %3;" : "=l"(d) : "l"(a), "l"(b), "l"(c));
    return d;
}
__device__ __forceinline__ u64 dup2(float v) {
    u64 r;
    asm("mov.b64 %0, {%1, %1};" : "=l"(r) : "f"(v));
    return r;
}
__device__ __forceinline__ void unpack2(u64 v, float& lo, float& hi) {
    asm("mov.b64 {%0, %1}, %2;" : "=f"(lo), "=f"(hi) : "l"(v));
}
__device__ __forceinline__ uint32_t smem_u32(const void* p) {
    uint32_t a;
    asm("{ .reg .u64 t; cvta.to.shared.u64 t, %1; cvt.u32.u64 %0, t; }"
        : "=r"(a) : "l"(p));
    return a;
}
__device__ __forceinline__ void mbar_wait(uint32_t mbar, uint32_t parity) {
    asm volatile(
        "{\n\t"
        ".reg .pred P1;\n\t"
        "WL_%=:\n\t"
        "mbarrier.try_wait.parity.acquire.cta.shared::cta.b64 P1, [%0], %1, 0x989680;\n\t"
        "@P1 bra.uni WD_%=;\n\t"
        "bra.uni WL_%=;\n\t"
        "WD_%=:\n\t"
        "}"
        :: "r"(mbar), "r"(parity) : "memory");
}
__device__ __forceinline__ void issue_chunk(uint32_t bar, uint32_t dst,
                                            const unsigned char* src) {
    asm volatile("mbarrier.arrive.expect_tx.shared.b64 _, [%0], %1;"
                 :: "r"(bar), "r"(CHUNK_B) : "memory");
    asm volatile(
        "cp.async.bulk.shared::cluster.global.mbarrier::complete_tx::bytes "
        "[%0], [%1], %2, [%3];"
        :: "r"(dst), "l"(src), "r"(CHUNK_B), "r"(bar) : "memory");
}

__global__ void __launch_bounds__(128)
interaction_kernel(const float* __restrict__ premise,
                   const float* __restrict__ hyp,
                   const float* __restrict__ kern,
                   float* __restrict__ out)
{
    extern __shared__ __align__(128) unsigned char smem_raw[];

    const int h   = blockIdx.x;      // 0..95
    const int p   = blockIdx.y;      // 0..95
    const int tid = threadIdx.x;     // 0..127
    const int w   = tid >> 5;        // warp: rows ir ≡ w (mod 4) within chunk
    const int l   = tid & 31;        // lane: columns 4l..4l+3

    const uint32_t sbase = smem_u32(smem_raw);
    u64* pre_d = reinterpret_cast<u64*>(smem_raw + PRE_OFF);
    __shared__ float red[4][NB];

    const unsigned char* ksrc = reinterpret_cast<const unsigned char*>(
        kern + (((size_t)(p * NH + h)) << 14));

    // One mbarrier per stage (single expect_tx arrival per phase).
    if (tid == 0) {
#pragma unroll
        for (int s = 0; s < STAGES; s++)
            asm volatile("mbarrier.init.shared.b64 [%0], %1;"
                         :: "r"(sbase + BAR_OFF + 8 * s), "r"(1) : "memory");
    }
    __syncthreads();

    // Prologue: fill the ring (chunks 0..2 -> stages 0..2).
    if (tid == 0) {
#pragma unroll
        for (int s = 0; s < STAGES; s++)
            issue_chunk(sbase + BAR_OFF + 8 * s,
                        sbase + K_OFF + s * CHUNK_B,
                        ksrc + (size_t)s * CHUNK_B);
    }

    // Stage premise[:, p, :] duplicated: pre_d[i*8+b] = (v, v)
#pragma unroll
    for (int r = 0; r < 8; r++) {
        int idx = tid + r * 128;
        int i = idx >> 3;
        int b = idx & 7;
        pre_d[idx] = dup2(premise[((size_t)b * NP + p) * ND + i]);
    }
    __syncthreads();

    const ulonglong2* pre2 = reinterpret_cast<const ulonglong2*>(pre_d);
    const ulonglong2* kbuf = reinterpret_cast<const ulonglong2*>(smem_raw + K_OFF);

    // acc[b][jp]: f32x2 accumulator for columns (4l+2jp, 4l+2jp+1), batch b
    u64 acc[NB][2];
#pragma unroll
    for (int b = 0; b < NB; b++) { acc[b][0] = 0ull; acc[b][1] = 0ull; }

#pragma unroll
    for (int c = 0; c < NCHUNKS; c++) {
        const int stage  = c % STAGES;            // constant under unroll
        const int parity = (c / STAGES) & 1;      // constant under unroll
        mbar_wait(sbase + BAR_OFF + 8 * stage, parity);

#pragma unroll
        for (int r = 0; r < CHUNK_ROWS / 4; r++) {
            const int ir = w + 4 * r;                 // row within chunk
            const int i  = c * CHUNK_ROWS + ir;       // row within tile
            ulonglong2 kv = kbuf[stage * 512 + ir * 32 + l];  // LDS.128
            ulonglong2 pr01 = pre2[i * 4 + 0];        // broadcast LDS.128
            ulonglong2 pr23 = pre2[i * 4 + 1];
            ulonglong2 pr45 = pre2[i * 4 + 2];
            ulonglong2 pr67 = pre2[i * 4 + 3];
            u64 pr[NB] = { pr01.x, pr01.y, pr23.x, pr23.y,
                           pr45.x, pr45.y, pr67.x, pr67.y };
#pragma unroll
            for (int b = 0; b < NB; b++) {
                acc[b][0] = fma2(kv.x, pr[b], acc[b][0]);
                acc[b][1] = fma2(kv.y, pr[b], acc[b][1]);
            }
        }

        // Recycle this stage for chunk c+3 (buffer-safe after the sync).
        if (c < NCHUNKS - STAGES) {
            __syncthreads();
            if (tid == 0)
                issue_chunk(sbase + BAR_OFF + 8 * stage,
                            sbase + K_OFF + stage * CHUNK_B,
                            ksrc + (size_t)(c + STAGES) * CHUNK_B);
        }
    }

    // Epilogue: fold hypothesis[b, h, 4l..4l+3] (float4 = two f32x2 pairs)
    float s[NB];
#pragma unroll
    for (int b = 0; b < NB; b++) {
        ulonglong2 hv = *reinterpret_cast<const ulonglong2*>(
            &hyp[((size_t)b * NH + h) * ND + 4 * l]);
        u64 t = fma2(acc[b][0], hv.x, 0ull);
        t = fma2(acc[b][1], hv.y, t);
        float lo, hi;
        unpack2(t, lo, hi);
        s[b] = lo + hi;
    }

    // Reduce over 32 lanes (j dimension)
#pragma unroll
    for (int off = 16; off; off >>= 1) {
#pragma unroll
        for (int b = 0; b < NB; b++)
            s[b] += __shfl_down_sync(0xffffffffu, s[b], off);
    }

    if (l == 0) {
#pragma unroll
        for (int b = 0; b < NB; b++) red[w][b] = s[b];
    }
    __syncthreads();

    if (tid < NB) {
        float v = red[0][tid] + red[1][tid] + red[2][tid] + red[3][tid];
        out[((size_t)tid * NP + p) * NH + h] = v;
    }
}

extern "C" void kernel_launch(void* const* d_in, const int* in_sizes, int n_in,
                              void* d_out, int out_size) {
    const float* premise = (const float*)d_in[0];  // (8, 96, 128)
    const float* hyp     = (const float*)d_in[1];  // (8, 96, 128)
    const float* kern    = (const float*)d_in[2];  // (96, 96, 128, 128)
    float* out = (float*)d_out;                    // (8, 96, 96)

    cudaFuncSetAttribute(interaction_kernel,
                         cudaFuncAttributeMaxDynamicSharedMemorySize, SMEM_TOTAL);
    dim3 grid(NH, NP);
    interaction_kernel<<<grid, 128, SMEM_TOTAL>>>(premise, hyp, kern, out);
}